// round 3
// baseline (speedup 1.0000x reference)
#include <cuda_runtime.h>
#include <math.h>

#define BATCH 64
#define NCAPS 2048
#define IDIM 16
#define DOUT 256
#define MLAN 96

// scratch (static device globals: allowed)
__device__ float g_u[(size_t)BATCH * NCAPS * DOUT];   // 134 MB
__device__ float g_C[(size_t)BATCH * DOUT * DOUT];    // 16 MB

// ---------------------------------------------------------------------------
// Pass 1: u[b,c,o] = sum_i caps[b,c,i] * W[c,i,o]
// one block per c, 256 threads (one per o)
// ---------------------------------------------------------------------------
__global__ void u_kernel(const float* __restrict__ caps, const float* __restrict__ W)
{
    int c = blockIdx.x;
    __shared__ __align__(16) float caps_s[BATCH][IDIM];   // 4KB
    __shared__ __align__(16) float w_s[IDIM][DOUT];       // 16KB
    int t = threadIdx.x;

    for (int idx = t; idx < BATCH * IDIM; idx += 256) {
        int b = idx >> 4, i = idx & 15;
        caps_s[b][i] = caps[(size_t)b * (NCAPS * IDIM) + (size_t)c * IDIM + i];
    }
    for (int idx = t; idx < IDIM * DOUT; idx += 256)
        ((float*)w_s)[idx] = W[(size_t)c * (IDIM * DOUT) + idx];
    __syncthreads();

    float wr[IDIM];
#pragma unroll
    for (int i = 0; i < IDIM; i++) wr[i] = w_s[i][t];

    for (int b = 0; b < BATCH; b++) {
        const float4* cp = (const float4*)caps_s[b];
        float acc = 0.f;
#pragma unroll
        for (int q = 0; q < 4; q++) {
            float4 cv = cp[q];
            acc += cv.x * wr[q * 4 + 0] + cv.y * wr[q * 4 + 1]
                 + cv.z * wr[q * 4 + 2] + cv.w * wr[q * 4 + 3];
        }
        g_u[(size_t)b * (NCAPS * DOUT) + (size_t)c * DOUT + t] = acc;
    }
}

// ---------------------------------------------------------------------------
// Pass 2: C[b] = u_b^T u_b   (batched SYRK, computed as full GEMM for now)
// 128x128 tile per block, 8x8 per thread, BK=16
// ---------------------------------------------------------------------------
#define BK 16
__global__ void __launch_bounds__(256, 2) syrk_kernel()
{
    int b  = blockIdx.z;
    int d0 = blockIdx.y * 128;
    int e0 = blockIdx.x * 128;
    __shared__ __align__(16) float As[BK][128];
    __shared__ __align__(16) float Bs[BK][128];
    int t = threadIdx.x;
    int tx = t & 15, ty = t >> 4;

    const float* ub = g_u + (size_t)b * NCAPS * DOUT;
    float acc[8][8];
#pragma unroll
    for (int i = 0; i < 8; i++)
#pragma unroll
        for (int j = 0; j < 8; j++) acc[i][j] = 0.f;

    for (int c0 = 0; c0 < NCAPS; c0 += BK) {
#pragma unroll
        for (int l = 0; l < 2; l++) {
            int idx = t + l * 256;
            int r = idx >> 5, cc = (idx & 31) * 4;
            *(float4*)&As[r][cc] = *(const float4*)&ub[(size_t)(c0 + r) * DOUT + d0 + cc];
            *(float4*)&Bs[r][cc] = *(const float4*)&ub[(size_t)(c0 + r) * DOUT + e0 + cc];
        }
        __syncthreads();
#pragma unroll
        for (int k = 0; k < BK; k++) {
            float a[8], bb[8];
            *(float4*)(a)      = *(float4*)&As[k][ty * 8];
            *(float4*)(a + 4)  = *(float4*)&As[k][ty * 8 + 4];
            *(float4*)(bb)     = *(float4*)&Bs[k][tx * 8];
            *(float4*)(bb + 4) = *(float4*)&Bs[k][tx * 8 + 4];
#pragma unroll
            for (int i = 0; i < 8; i++)
#pragma unroll
                for (int j = 0; j < 8; j++) acc[i][j] += a[i] * bb[j];
        }
        __syncthreads();
    }
    float* Cb = g_C + (size_t)b * DOUT * DOUT;
#pragma unroll
    for (int i = 0; i < 8; i++) {
        int d = d0 + ty * 8 + i;
#pragma unroll
        for (int j = 0; j < 8; j += 4) {
            float4 v = make_float4(acc[i][j], acc[i][j+1], acc[i][j+2], acc[i][j+3]);
            *(float4*)&Cb[(size_t)d * DOUT + e0 + tx * 8 + j] = v;
        }
    }
}

// ---------------------------------------------------------------------------
// Pass 3: top eigenvector of each C[b] via Lanczos(m=96) + full CGS2 reorth.
// One block per batch, 256 threads. Krylov basis V in dynamic smem.
// ---------------------------------------------------------------------------
__device__ __forceinline__ float blk_sum(float v, float* red)
{
#pragma unroll
    for (int o = 16; o; o >>= 1) v += __shfl_xor_sync(0xffffffffu, v, o);
    int lane = threadIdx.x & 31, wid = threadIdx.x >> 5;
    __syncthreads();
    if (lane == 0) red[wid] = v;
    __syncthreads();
    float s = red[0];
#pragma unroll
    for (int i = 1; i < 8; i++) s += red[i];
    return s;
}

__device__ __forceinline__ float blk_max(float v, float* red)
{
#pragma unroll
    for (int o = 16; o; o >>= 1) v = fmaxf(v, __shfl_xor_sync(0xffffffffu, v, o));
    int lane = threadIdx.x & 31, wid = threadIdx.x >> 5;
    __syncthreads();
    if (lane == 0) red[wid] = v;
    __syncthreads();
    float s = red[0];
#pragma unroll
    for (int i = 1; i < 8; i++) s = fmaxf(s, red[i]);
    return s;
}

__global__ void lanczos_kernel(float* __restrict__ out)
{
    extern __shared__ float sh[];
    float* V     = sh;                       // (MLAN+1) x 256
    float* wv    = V + (MLAN + 1) * 256;     // 256
    float* alpha = wv + 256;                 // MLAN
    float* beta  = alpha + MLAN;             // MLAN
    float* coef  = beta + MLAN;              // MLAN
    float* yv    = coef + MLAN;              // MLAN
    float* tdd   = yv + MLAN;                // MLAN
    float* tu1   = tdd + MLAN;               // MLAN
    float* tu2   = tu1 + MLAN;               // MLAN
    float* red   = tu2 + MLAN;               // 8
    float* ssc   = red + 8;                  // 8 scalars

    __shared__ int midx;

    int t = threadIdx.x;
    int lane = t & 31, wid = t >> 5;
    int b = blockIdx.x;
    const float* C = g_C + (size_t)b * DOUT * DOUT;

    // deterministic start vector
    float x = __sinf((float)t * 1.7f + 0.5f) + 0.01f;
    float nn = blk_sum(x * x, red);
    x *= rsqrtf(nn);
    V[t] = x;
    __syncthreads();

    int m_eff = MLAN;
    for (int j = 0; j < MLAN; j++) {
        // ---- matvec: wv = C * V[j] ----
        const float4* v4 = (const float4*)(V + j * 256);
        for (int d = wid; d < 256; d += 8) {
            const float4* row4 = (const float4*)(C + (size_t)d * 256);
            float s = 0.f;
#pragma unroll
            for (int q = 0; q < 2; q++) {
                float4 rv = row4[lane + q * 32];
                float4 vv = v4[lane + q * 32];
                s += rv.x * vv.x + rv.y * vv.y + rv.z * vv.z + rv.w * vv.w;
            }
#pragma unroll
            for (int o = 16; o; o >>= 1) s += __shfl_xor_sync(0xffffffffu, s, o);
            if (lane == 0) wv[d] = s;
        }
        __syncthreads();

        // alpha_j = v_j . w
        float a = blk_sum(V[j * 256 + t] * wv[t], red);
        if (t == 0) alpha[j] = a;

        float wnew = wv[t] - a * V[j * 256 + t];
        if (j > 0) wnew -= beta[j - 1] * V[(j - 1) * 256 + t];

        // ---- full reorthogonalization, CGS x2 ----
        for (int pass = 0; pass < 2; pass++) {
            __syncthreads();
            wv[t] = wnew;
            __syncthreads();
            for (int i = wid; i <= j; i += 8) {
                const float4* vi4 = (const float4*)(V + i * 256);
                const float4* w4  = (const float4*)wv;
                float s = 0.f;
#pragma unroll
                for (int q = 0; q < 2; q++) {
                    float4 vv = vi4[lane + q * 32];
                    float4 ww = w4[lane + q * 32];
                    s += vv.x * ww.x + vv.y * ww.y + vv.z * ww.z + vv.w * ww.w;
                }
#pragma unroll
                for (int o = 16; o; o >>= 1) s += __shfl_xor_sync(0xffffffffu, s, o);
                if (lane == 0) coef[i] = s;
            }
            __syncthreads();
            float corr = 0.f;
            for (int i = 0; i <= j; i++) corr += coef[i] * V[i * 256 + t];
            wnew = wv[t] - corr;
        }

        float b2 = blk_sum(wnew * wnew, red);
        float bn = sqrtf(b2);
        if (bn < 1e-20f) { m_eff = j + 1; break; }
        if (t == 0) beta[j] = bn;
        V[(j + 1) * 256 + t] = wnew / bn;
        __syncthreads();
    }

    // ---- tridiagonal top eigenpair (serial, thread 0) ----
    if (t == 0) {
        int m = m_eff;
        // Gershgorin bounds
        float lo = alpha[0], hi = alpha[0];
        for (int i = 0; i < m; i++) {
            float r = (i > 0 ? fabsf(beta[i - 1]) : 0.f) + (i < m - 1 ? fabsf(beta[i]) : 0.f);
            lo = fminf(lo, alpha[i] - r);
            hi = fmaxf(hi, alpha[i] + r);
        }
        // Sturm bisection for lambda_max
        for (int it = 0; it < 64; it++) {
            float mid = 0.5f * (lo + hi);
            int cnt = 0;
            float d = alpha[0] - mid;
            if (d < 0.f) cnt++;
            for (int i = 1; i < m; i++) {
                if (d == 0.f) d = -1e-30f;
                d = alpha[i] - mid - beta[i - 1] * beta[i - 1] / d;
                if (d < 0.f) cnt++;
            }
            if (cnt >= m) hi = mid; else lo = mid;
        }
        float lam = 0.5f * (lo + hi);

        // inverse iteration with partial-pivot tridiag LU, 2 rounds
        for (int it = 0; it < 2; it++) {
            if (it == 0) for (int i = 0; i < m; i++) yv[i] = 1.f;
            for (int i = 0; i < m; i++) {
                tdd[i] = alpha[i] - lam;
                tu1[i] = (i < m - 1) ? beta[i] : 0.f;
                tu2[i] = 0.f;
            }
            for (int i = 0; i < m - 1; i++) {
                float p = tdd[i], q = tu1[i], r = tu2[i];
                float s = beta[i];
                float uu = tdd[i + 1], vvv = tu1[i + 1];
                float yi = yv[i], yi1 = yv[i + 1];
                if (fabsf(s) > fabsf(p)) {
                    float tmp;
                    tmp = p; p = s; s = tmp;
                    tmp = q; q = uu; uu = tmp;
                    tmp = r; r = vvv; vvv = tmp;
                    tmp = yi; yi = yi1; yi1 = tmp;
                }
                if (p == 0.f) p = 1e-30f;
                float mf = s / p;
                tdd[i] = p; tu1[i] = q; tu2[i] = r; yv[i] = yi;
                tdd[i + 1] = uu - mf * q;
                tu1[i + 1] = vvv - mf * r;
                tu2[i + 1] = 0.f;
                yv[i + 1] = yi1 - mf * yi;
            }
            if (tdd[m - 1] == 0.f) tdd[m - 1] = 1e-30f;
            yv[m - 1] /= tdd[m - 1];
            if (m >= 2) yv[m - 2] = (yv[m - 2] - tu1[m - 2] * yv[m - 1]) / tdd[m - 2];
            for (int i = m - 3; i >= 0; i--)
                yv[i] = (yv[i] - tu1[i] * yv[i + 1] - tu2[i] * yv[i + 2]) / tdd[i];
            float s2 = 0.f;
            for (int i = 0; i < m; i++) s2 += yv[i] * yv[i];
            float inv = rsqrtf(s2);
            for (int i = 0; i < m; i++) yv[i] *= inv;
        }
        midx = 1 << 30;
    }
    __syncthreads();

    // Ritz vector v = sum_j y_j V_j  (component t)
    float vr = 0.f;
    for (int i = 0; i < m_eff; i++) vr += yv[i] * V[i * 256 + t];
    float n2 = blk_sum(vr * vr, red);
    vr *= rsqrtf(n2);

    // sign fix: make component with largest |.| (first such index) positive
    float av = fabsf(vr);
    float mx = blk_max(av, red);
    if (av == mx) atomicMin(&midx, t);
    __syncthreads();
    if (t == midx) ssc[0] = (vr >= 0.f) ? 1.f : -1.f;
    __syncthreads();

    out[(size_t)b * 256 + t] = vr * ssc[0];
}

// ---------------------------------------------------------------------------
extern "C" void kernel_launch(void* const* d_in, const int* in_sizes, int n_in,
                              void* d_out, int out_size)
{
    const float* caps = (const float*)d_in[0];   // (64, 2048, 16)
    const float* W    = (const float*)d_in[1];   // (2048, 16, 256)
    float* out        = (float*)d_out;           // (64, 16, 16)

    u_kernel<<<NCAPS, 256>>>(caps, W);

    dim3 g2(2, 2, BATCH);
    syrk_kernel<<<g2, 256>>>();

    size_t smem = ((MLAN + 1) * 256 + 256 + 7 * MLAN + 16) * sizeof(float);
    cudaFuncSetAttribute(lanczos_kernel, cudaFuncAttributeMaxDynamicSharedMemorySize, (int)smem);
    lanczos_kernel<<<BATCH, 256, smem>>>(out);
}

// round 5
// speedup vs baseline: 1.9387x; 1.9387x over previous
#include <cuda_runtime.h>
#include <math.h>

#define BATCH 64
#define NCAPS 2048
#define IDIM 16
#define DOUT 256
#define MLAN 72

typedef unsigned long long u64;

__device__ float g_u[(size_t)BATCH * NCAPS * DOUT];   // 134 MB
__device__ float g_C[(size_t)BATCH * DOUT * DOUT];    // 16 MB

// ---------------- packed f32x2 helpers ----------------
__device__ __forceinline__ void ffma2(u64 &d, u64 a, u64 b) {
    asm("fma.rn.f32x2 %0, %1, %2, %0;" : "+l"(d) : "l"(a), "l"(b));
}
__device__ __forceinline__ u64 pack2(float x, float y) {
    u64 r; asm("mov.b64 %0, {%1, %2};" : "=l"(r) : "f"(x), "f"(y)); return r;
}
__device__ __forceinline__ void unpack2(float &x, float &y, u64 v) {
    asm("mov.b64 {%0, %1}, %2;" : "=f"(x), "=f"(y) : "l"(v));
}

// ---------------------------------------------------------------------------
// Pass 1: u[b,c,o] = sum_i caps[b,c,i] * W[c,i,o]
// grid (NCAPS, 4): each block does 16 batches for one capsule
// ---------------------------------------------------------------------------
__global__ void u_kernel(const float* __restrict__ caps, const float* __restrict__ W)
{
    int c  = blockIdx.x;
    int b0 = blockIdx.y * 16;
    __shared__ __align__(16) float caps_s[16][IDIM];
    __shared__ __align__(16) float w_s[IDIM][DOUT];
    int t = threadIdx.x;

    if (t < 16 * IDIM) {
        int b = t >> 4, i = t & 15;
        caps_s[b][i] = caps[(size_t)(b0 + b) * (NCAPS * IDIM) + (size_t)c * IDIM + i];
    }
    for (int idx = t; idx < IDIM * DOUT; idx += 256)
        ((float*)w_s)[idx] = W[(size_t)c * (IDIM * DOUT) + idx];
    __syncthreads();

    float wr[IDIM];
#pragma unroll
    for (int i = 0; i < IDIM; i++) wr[i] = w_s[i][t];

#pragma unroll 4
    for (int b = 0; b < 16; b++) {
        const float4* cp = (const float4*)caps_s[b];
        float acc = 0.f;
#pragma unroll
        for (int q = 0; q < 4; q++) {
            float4 cv = cp[q];
            acc += cv.x * wr[q * 4 + 0] + cv.y * wr[q * 4 + 1]
                 + cv.z * wr[q * 4 + 2] + cv.w * wr[q * 4 + 3];
        }
        g_u[(size_t)(b0 + b) * (NCAPS * DOUT) + (size_t)c * DOUT + t] = acc;
    }
}

// ---------------------------------------------------------------------------
// Pass 2: C[b] = u_b^T u_b — symmetric: compute tiles (0,0),(1,1),(1,0) only.
// 128x128 per block, 8x8 per thread, BK=16, packed fma.rn.f32x2 inner loop.
// ---------------------------------------------------------------------------
#define BK 16
__global__ void __launch_bounds__(256, 2) syrk_kernel()
{
    int b = blockIdx.z;
    int which = blockIdx.x;              // 0:(0,0) 1:(1,1) 2:(1,0)
    int d0 = (which == 0) ? 0 : 128;     // output row tile
    int e0 = (which == 1) ? 128 : 0;     // output col tile

    __shared__ __align__(16) float As[BK][128];
    __shared__ __align__(16) float Bs[BK][128];
    int t = threadIdx.x;
    int tx = t & 15, ty = t >> 4;

    const float* ub = g_u + (size_t)b * NCAPS * DOUT;

    u64 acc2[8][4];
#pragma unroll
    for (int i = 0; i < 8; i++)
#pragma unroll
        for (int j = 0; j < 4; j++) acc2[i][j] = 0ull;

    for (int c0 = 0; c0 < NCAPS; c0 += BK) {
#pragma unroll
        for (int l = 0; l < 2; l++) {
            int idx = t + l * 256;
            int r = idx >> 5, cc = (idx & 31) * 4;
            *(float4*)&As[r][cc] = *(const float4*)&ub[(size_t)(c0 + r) * DOUT + d0 + cc];
            *(float4*)&Bs[r][cc] = *(const float4*)&ub[(size_t)(c0 + r) * DOUT + e0 + cc];
        }
        __syncthreads();
#pragma unroll
        for (int k = 0; k < BK; k++) {
            float4 A1 = *(float4*)&As[k][ty * 8];
            float4 A2 = *(float4*)&As[k][ty * 8 + 4];
            float4 B1 = *(float4*)&Bs[k][tx * 8];
            float4 B2 = *(float4*)&Bs[k][tx * 8 + 4];
            u64 b2[4] = { pack2(B1.x, B1.y), pack2(B1.z, B1.w),
                          pack2(B2.x, B2.y), pack2(B2.z, B2.w) };
            float a[8] = {A1.x, A1.y, A1.z, A1.w, A2.x, A2.y, A2.z, A2.w};
#pragma unroll
            for (int i = 0; i < 8; i++) {
                u64 ad = pack2(a[i], a[i]);
#pragma unroll
                for (int j = 0; j < 4; j++) ffma2(acc2[i][j], ad, b2[j]);
            }
        }
        __syncthreads();
    }

    float* Cb = g_C + (size_t)b * DOUT * DOUT;
#pragma unroll
    for (int i = 0; i < 8; i++) {
        int d = d0 + ty * 8 + i;
        float v[8];
#pragma unroll
        for (int j = 0; j < 4; j++) unpack2(v[2 * j], v[2 * j + 1], acc2[i][j]);
        *(float4*)&Cb[(size_t)d * DOUT + e0 + tx * 8]     = make_float4(v[0], v[1], v[2], v[3]);
        *(float4*)&Cb[(size_t)d * DOUT + e0 + tx * 8 + 4] = make_float4(v[4], v[5], v[6], v[7]);
    }
}

// mirror the (1,0) tile into (0,1): C[y][x] = C[x][y], y<128<=x
__global__ void mirror_kernel()
{
    __shared__ float tile[32][33];
    float* Cb = g_C + (size_t)blockIdx.z * DOUT * DOUT;
    int sx = 128 + blockIdx.x * 32;  // source rows
    int sy = blockIdx.y * 32;        // source cols
    int tx = threadIdx.x, ty = threadIdx.y;   // 32x8
#pragma unroll
    for (int k = 0; k < 32; k += 8)
        tile[ty + k][tx] = Cb[(size_t)(sx + ty + k) * DOUT + sy + tx];
    __syncthreads();
#pragma unroll
    for (int k = 0; k < 32; k += 8)
        Cb[(size_t)(sy + ty + k) * DOUT + sx + tx] = tile[tx][ty + k];
}

// ---------------------------------------------------------------------------
// Pass 3: Lanczos(m=72) + CGS2 reorth, parallel Sturm, inverse iteration.
// ---------------------------------------------------------------------------
__device__ __forceinline__ float blk_sum(float v, float* red)
{
#pragma unroll
    for (int o = 16; o; o >>= 1) v += __shfl_xor_sync(0xffffffffu, v, o);
    int lane = threadIdx.x & 31, wid = threadIdx.x >> 5;
    __syncthreads();
    if (lane == 0) red[wid] = v;
    __syncthreads();
    float s = red[0];
#pragma unroll
    for (int i = 1; i < 8; i++) s += red[i];
    return s;
}

__device__ __forceinline__ float blk_max(float v, float* red)
{
#pragma unroll
    for (int o = 16; o; o >>= 1) v = fmaxf(v, __shfl_xor_sync(0xffffffffu, v, o));
    int lane = threadIdx.x & 31, wid = threadIdx.x >> 5;
    __syncthreads();
    if (lane == 0) red[wid] = v;
    __syncthreads();
    float s = red[0];
#pragma unroll
    for (int i = 1; i < 8; i++) s = fmaxf(s, red[i]);
    return s;
}

__device__ __forceinline__ float blk_min(float v, float* red)
{
#pragma unroll
    for (int o = 16; o; o >>= 1) v = fminf(v, __shfl_xor_sync(0xffffffffu, v, o));
    int lane = threadIdx.x & 31, wid = threadIdx.x >> 5;
    __syncthreads();
    if (lane == 0) red[wid] = v;
    __syncthreads();
    float s = red[0];
#pragma unroll
    for (int i = 1; i < 8; i++) s = fminf(s, red[i]);
    return s;
}

__global__ void lanczos_kernel(float* __restrict__ out)
{
    extern __shared__ float sh[];
    float* V     = sh;                       // (MLAN+1) x 256
    float* wv    = V + (MLAN + 1) * 256;     // 256
    float* alpha = wv + 256;                 // MLAN
    float* beta  = alpha + MLAN;             // MLAN
    float* coef  = beta + MLAN;              // MLAN
    float* yv    = coef + MLAN;              // MLAN
    float* tdd   = yv + MLAN;                // MLAN (also bsq scratch)
    float* tu1   = tdd + MLAN;               // MLAN
    float* tu2   = tu1 + MLAN;               // MLAN
    float* red   = tu2 + MLAN;               // 8
    float* ssc   = red + 8;                  // 8

    __shared__ int midx;

    int t = threadIdx.x;
    int lane = t & 31, wid = t >> 5;
    int b = blockIdx.x;
    const float* C = g_C + (size_t)b * DOUT * DOUT;

    float x = __sinf((float)t * 1.7f + 0.5f) + 0.01f;
    float nn = blk_sum(x * x, red);
    x *= rsqrtf(nn);
    V[t] = x;
    __syncthreads();

    int m_eff = MLAN;
    int rbase = wid * 32;
    for (int j = 0; j < MLAN; j++) {
        // ---- matvec: wv = C * V[j], 4-row chunks per warp ----
        {
            const float4* v4 = (const float4*)(V + j * 256);
            float4 va = v4[lane];
            float4 vb = v4[lane + 32];
            for (int r = 0; r < 32; r += 4) {
                float s0, s1, s2, s3;
                {
                    const float4* r4 = (const float4*)(C + (size_t)(rbase + r) * 256);
                    float4 c1 = r4[lane], c2 = r4[lane + 32];
                    s0 = c1.x*va.x + c1.y*va.y + c1.z*va.z + c1.w*va.w
                       + c2.x*vb.x + c2.y*vb.y + c2.z*vb.z + c2.w*vb.w;
                }
                {
                    const float4* r4 = (const float4*)(C + (size_t)(rbase + r + 1) * 256);
                    float4 c1 = r4[lane], c2 = r4[lane + 32];
                    s1 = c1.x*va.x + c1.y*va.y + c1.z*va.z + c1.w*va.w
                       + c2.x*vb.x + c2.y*vb.y + c2.z*vb.z + c2.w*vb.w;
                }
                {
                    const float4* r4 = (const float4*)(C + (size_t)(rbase + r + 2) * 256);
                    float4 c1 = r4[lane], c2 = r4[lane + 32];
                    s2 = c1.x*va.x + c1.y*va.y + c1.z*va.z + c1.w*va.w
                       + c2.x*vb.x + c2.y*vb.y + c2.z*vb.z + c2.w*vb.w;
                }
                {
                    const float4* r4 = (const float4*)(C + (size_t)(rbase + r + 3) * 256);
                    float4 c1 = r4[lane], c2 = r4[lane + 32];
                    s3 = c1.x*va.x + c1.y*va.y + c1.z*va.z + c1.w*va.w
                       + c2.x*vb.x + c2.y*vb.y + c2.z*vb.z + c2.w*vb.w;
                }
#pragma unroll
                for (int o = 16; o; o >>= 1) {
                    s0 += __shfl_xor_sync(0xffffffffu, s0, o);
                    s1 += __shfl_xor_sync(0xffffffffu, s1, o);
                    s2 += __shfl_xor_sync(0xffffffffu, s2, o);
                    s3 += __shfl_xor_sync(0xffffffffu, s3, o);
                }
                if (lane == 0) {
                    wv[rbase + r]     = s0;
                    wv[rbase + r + 1] = s1;
                    wv[rbase + r + 2] = s2;
                    wv[rbase + r + 3] = s3;
                }
            }
        }
        __syncthreads();

        float a = blk_sum(V[j * 256 + t] * wv[t], red);
        if (t == 0) alpha[j] = a;

        float wnew = wv[t] - a * V[j * 256 + t];
        if (j > 0) wnew -= beta[j - 1] * V[(j - 1) * 256 + t];

        // ---- CGS x2 full reorthogonalization ----
        for (int pass = 0; pass < 2; pass++) {
            __syncthreads();
            wv[t] = wnew;
            __syncthreads();
            float4 wa = ((const float4*)wv)[lane];
            float4 wb = ((const float4*)wv)[lane + 32];
            for (int i0 = wid * 4; i0 <= j; i0 += 32) {
                float s[4];
#pragma unroll
                for (int q = 0; q < 4; q++) {
                    int iq = (i0 + q <= j) ? (i0 + q) : j;
                    const float4* vi4 = (const float4*)(V + iq * 256);
                    float4 c1 = vi4[lane], c2 = vi4[lane + 32];
                    s[q] = c1.x*wa.x + c1.y*wa.y + c1.z*wa.z + c1.w*wa.w
                         + c2.x*wb.x + c2.y*wb.y + c2.z*wb.z + c2.w*wb.w;
                }
#pragma unroll
                for (int o = 16; o; o >>= 1) {
                    s[0] += __shfl_xor_sync(0xffffffffu, s[0], o);
                    s[1] += __shfl_xor_sync(0xffffffffu, s[1], o);
                    s[2] += __shfl_xor_sync(0xffffffffu, s[2], o);
                    s[3] += __shfl_xor_sync(0xffffffffu, s[3], o);
                }
                if (lane == 0) {
#pragma unroll
                    for (int q = 0; q < 4; q++)
                        if (i0 + q <= j) coef[i0 + q] = s[q];
                }
            }
            __syncthreads();
            float corr = 0.f;
            for (int i = 0; i <= j; i++) corr += coef[i] * V[i * 256 + t];
            wnew = wv[t] - corr;
        }

        float b2 = blk_sum(wnew * wnew, red);
        float bn = sqrtf(b2);
        if (bn < 1e-20f) { m_eff = j + 1; break; }
        if (t == 0) beta[j] = bn;
        V[(j + 1) * 256 + t] = wnew / bn;
        __syncthreads();
    }

    int m = m_eff;

    // ---- Gershgorin bounds (parallel) ----
    float gl = 1e30f, gh = -1e30f;
    if (t < m) {
        float r = (t > 0 ? fabsf(beta[t - 1]) : 0.f) + (t < m - 1 ? fabsf(beta[t]) : 0.f);
        gl = alpha[t] - r;
        gh = alpha[t] + r;
    }
    float lo = blk_min(gl, red);
    float hi = blk_max(gh, red);

    if (t < m - 1) tdd[t] = beta[t] * beta[t];   // bsq scratch
    __syncthreads();

    // ---- parallel Sturm: 256 points x 4 rounds ----
    for (int r = 0; r < 4; r++) {
        float xx = lo + (hi - lo) * ((float)(t + 1) * (1.f / 257.f));
        int cnt = 0;
        float d = alpha[0] - xx;
        if (d < 0.f) cnt++;
        for (int i = 1; i < m; i++) {
            if (fabsf(d) < 1e-30f) d = (d < 0.f) ? -1e-30f : ((d > 0.f) ? 1e-30f : -1e-30f);
            d = alpha[i] - xx - __fdividef(tdd[i - 1], d);
            if (d < 0.f) cnt++;
        }
        float cl = (cnt < m)  ? xx : -1e30f;
        float ch = (cnt >= m) ? xx :  1e30f;
        float nl = blk_max(cl, red);
        float nh = blk_min(ch, red);
        lo = fmaxf(lo, nl);
        hi = fminf(hi, nh);
    }
    float lam = 0.5f * (lo + hi);
    __syncthreads();

    // ---- inverse iteration (serial, thread 0) ----
    if (t == 0) {
        for (int it = 0; it < 2; it++) {
            if (it == 0) for (int i = 0; i < m; i++) yv[i] = 1.f;
            for (int i = 0; i < m; i++) {
                tdd[i] = alpha[i] - lam;
                tu1[i] = (i < m - 1) ? beta[i] : 0.f;
                tu2[i] = 0.f;
            }
            for (int i = 0; i < m - 1; i++) {
                float p = tdd[i], q = tu1[i], rr = tu2[i];
                float s = beta[i];
                float uu = tdd[i + 1], vvv = tu1[i + 1];
                float yi = yv[i], yi1 = yv[i + 1];
                if (fabsf(s) > fabsf(p)) {
                    float tmp;
                    tmp = p; p = s; s = tmp;
                    tmp = q; q = uu; uu = tmp;
                    tmp = rr; rr = vvv; vvv = tmp;
                    tmp = yi; yi = yi1; yi1 = tmp;
                }
                if (p == 0.f) p = 1e-30f;
                float mf = s / p;
                tdd[i] = p; tu1[i] = q; tu2[i] = rr; yv[i] = yi;
                tdd[i + 1] = uu - mf * q;
                tu1[i + 1] = vvv - mf * rr;
                tu2[i + 1] = 0.f;
                yv[i + 1] = yi1 - mf * yi;
            }
            if (tdd[m - 1] == 0.f) tdd[m - 1] = 1e-30f;
            yv[m - 1] /= tdd[m - 1];
            if (m >= 2) yv[m - 2] = (yv[m - 2] - tu1[m - 2] * yv[m - 1]) / tdd[m - 2];
            for (int i = m - 3; i >= 0; i--)
                yv[i] = (yv[i] - tu1[i] * yv[i + 1] - tu2[i] * yv[i + 2]) / tdd[i];
            float s2 = 0.f;
            for (int i = 0; i < m; i++) s2 += yv[i] * yv[i];
            float inv = rsqrtf(s2);
            for (int i = 0; i < m; i++) yv[i] *= inv;
        }
        midx = 1 << 30;
    }
    __syncthreads();

    // Ritz vector
    float vr = 0.f;
    for (int i = 0; i < m; i++) vr += yv[i] * V[i * 256 + t];
    float n2 = blk_sum(vr * vr, red);
    vr *= rsqrtf(n2);

    float av = fabsf(vr);
    float mx = blk_max(av, red);
    if (av == mx) atomicMin(&midx, t);
    __syncthreads();
    if (t == midx) ssc[0] = (vr >= 0.f) ? 1.f : -1.f;
    __syncthreads();

    out[(size_t)b * 256 + t] = vr * ssc[0];
}

// ---------------------------------------------------------------------------
extern "C" void kernel_launch(void* const* d_in, const int* in_sizes, int n_in,
                              void* d_out, int out_size)
{
    const float* caps = (const float*)d_in[0];   // (64, 2048, 16)
    const float* W    = (const float*)d_in[1];   // (2048, 16, 256)
    float* out        = (float*)d_out;           // (64, 16, 16)

    dim3 g1(NCAPS, 4);
    u_kernel<<<g1, 256>>>(caps, W);

    dim3 g2(3, 1, BATCH);
    syrk_kernel<<<g2, 256>>>();

    dim3 gm(4, 4, BATCH);
    mirror_kernel<<<gm, dim3(32, 8)>>>();

    size_t smem = ((MLAN + 1) * 256 + 256 + 7 * MLAN + 16) * sizeof(float);
    cudaFuncSetAttribute(lanczos_kernel, cudaFuncAttributeMaxDynamicSharedMemorySize, (int)smem);
    lanczos_kernel<<<BATCH, 256, smem>>>(out);
}

// round 8
// speedup vs baseline: 2.4279x; 1.2523x over previous
#include <cuda_runtime.h>
#include <math.h>

#define BATCH 64
#define NCAPS 2048
#define IDIM 16
#define DOUT 256
#define MLAN 64
#define KSPLIT 3

typedef unsigned long long u64;

__device__ float g_u[(size_t)BATCH * NCAPS * DOUT];              // 134 MB
__device__ float g_C[(size_t)BATCH * DOUT * DOUT];               // 16 MB
__device__ float g_Cp[KSPLIT][(size_t)BATCH * DOUT * DOUT];      // 48 MB partials

// ---------------- packed f32x2 helpers ----------------
__device__ __forceinline__ void ffma2(u64 &d, u64 a, u64 b) {
    asm("fma.rn.f32x2 %0, %1, %2, %0;" : "+l"(d) : "l"(a), "l"(b));
}
__device__ __forceinline__ u64 pack2(float x, float y) {
    u64 r; asm("mov.b64 %0, {%1, %2};" : "=l"(r) : "f"(x), "f"(y)); return r;
}
__device__ __forceinline__ void unpack2(float &x, float &y, u64 v) {
    asm("mov.b64 {%0, %1}, %2;" : "=f"(x), "=f"(y) : "l"(v));
}

// ---------------------------------------------------------------------------
// Pass 1: u[b,c,o] = sum_i caps[b,c,i] * W[c,i,o]
// ---------------------------------------------------------------------------
__global__ void u_kernel(const float* __restrict__ caps, const float* __restrict__ W)
{
    int c  = blockIdx.x;
    int b0 = blockIdx.y * 16;
    __shared__ __align__(16) float caps_s[16][IDIM];
    __shared__ __align__(16) float w_s[IDIM][DOUT];
    int t = threadIdx.x;

    if (t < 16 * IDIM) {
        int b = t >> 4, i = t & 15;
        caps_s[b][i] = caps[(size_t)(b0 + b) * (NCAPS * IDIM) + (size_t)c * IDIM + i];
    }
    for (int idx = t; idx < IDIM * DOUT; idx += 256)
        ((float*)w_s)[idx] = W[(size_t)c * (IDIM * DOUT) + idx];
    __syncthreads();

    float wr[IDIM];
#pragma unroll
    for (int i = 0; i < IDIM; i++) wr[i] = w_s[i][t];

#pragma unroll 4
    for (int b = 0; b < 16; b++) {
        const float4* cp = (const float4*)caps_s[b];
        float acc = 0.f;
#pragma unroll
        for (int q = 0; q < 4; q++) {
            float4 cv = cp[q];
            acc += cv.x * wr[q * 4 + 0] + cv.y * wr[q * 4 + 1]
                 + cv.z * wr[q * 4 + 2] + cv.w * wr[q * 4 + 3];
        }
        g_u[(size_t)(b0 + b) * (NCAPS * DOUT) + (size_t)c * DOUT + t] = acc;
    }
}

// ---------------------------------------------------------------------------
// Pass 2: SYRK, K-split x3 into partial buffers.
// grid (3 tiles, KSPLIT, BATCH). tiles: 0:(0,0) 1:(1,1) 2:(1,0)
// ---------------------------------------------------------------------------
#define BK 16
__global__ void __launch_bounds__(256, 2) syrk_kernel()
{
    int b = blockIdx.z;
    int which = blockIdx.x;
    int ks = blockIdx.y;
    int d0 = (which == 0) ? 0 : 128;
    int e0 = (which == 1) ? 128 : 0;
    int kbeg = ks * 688;
    int kend = (ks == KSPLIT - 1) ? NCAPS : kbeg + 688;

    __shared__ __align__(16) float As[BK][128];
    __shared__ __align__(16) float Bs[BK][128];
    int t = threadIdx.x;
    int tx = t & 15, ty = t >> 4;

    const float* ub = g_u + (size_t)b * NCAPS * DOUT;

    u64 acc2[8][4];
#pragma unroll
    for (int i = 0; i < 8; i++)
#pragma unroll
        for (int j = 0; j < 4; j++) acc2[i][j] = 0ull;

    for (int c0 = kbeg; c0 < kend; c0 += BK) {
#pragma unroll
        for (int l = 0; l < 2; l++) {
            int idx = t + l * 256;
            int r = idx >> 5, cc = (idx & 31) * 4;
            *(float4*)&As[r][cc] = *(const float4*)&ub[(size_t)(c0 + r) * DOUT + d0 + cc];
            *(float4*)&Bs[r][cc] = *(const float4*)&ub[(size_t)(c0 + r) * DOUT + e0 + cc];
        }
        __syncthreads();
#pragma unroll
        for (int k = 0; k < BK; k++) {
            float4 A1 = *(float4*)&As[k][ty * 8];
            float4 A2 = *(float4*)&As[k][ty * 8 + 4];
            float4 B1 = *(float4*)&Bs[k][tx * 8];
            float4 B2 = *(float4*)&Bs[k][tx * 8 + 4];
            u64 b2[4] = { pack2(B1.x, B1.y), pack2(B1.z, B1.w),
                          pack2(B2.x, B2.y), pack2(B2.z, B2.w) };
            float a[8] = {A1.x, A1.y, A1.z, A1.w, A2.x, A2.y, A2.z, A2.w};
#pragma unroll
            for (int i = 0; i < 8; i++) {
                u64 ad = pack2(a[i], a[i]);
#pragma unroll
                for (int j = 0; j < 4; j++) ffma2(acc2[i][j], ad, b2[j]);
            }
        }
        __syncthreads();
    }

    float* Cb = g_Cp[ks] + (size_t)b * DOUT * DOUT;
#pragma unroll
    for (int i = 0; i < 8; i++) {
        int d = d0 + ty * 8 + i;
        float v[8];
#pragma unroll
        for (int j = 0; j < 4; j++) unpack2(v[2 * j], v[2 * j + 1], acc2[i][j]);
        *(float4*)&Cb[(size_t)d * DOUT + e0 + tx * 8]     = make_float4(v[0], v[1], v[2], v[3]);
        *(float4*)&Cb[(size_t)d * DOUT + e0 + tx * 8 + 4] = make_float4(v[4], v[5], v[6], v[7]);
    }
}

// sum the 3 K-split partials for the 3 computed tiles (deterministic)
__global__ void reduce_kernel()
{
    int b = blockIdx.y;
    int which = blockIdx.x;
    int d0 = (which == 0) ? 0 : 128;
    int e0 = (which == 1) ? 128 : 0;
    size_t base = (size_t)b * DOUT * DOUT;
    int t = threadIdx.x;
    for (int i = t; i < 128 * 32; i += 256) {       // 4096 float4 = tile
        int r = i >> 5, c4 = (i & 31);
        size_t off = base + (size_t)(d0 + r) * DOUT + e0 + c4 * 4;
        float4 a = *(const float4*)&g_Cp[0][off];
        float4 bb = *(const float4*)&g_Cp[1][off];
        float4 c = *(const float4*)&g_Cp[2][off];
        float4 s = make_float4(a.x + bb.x + c.x, a.y + bb.y + c.y,
                               a.z + bb.z + c.z, a.w + bb.w + c.w);
        *(float4*)&g_C[off] = s;
    }
}

// mirror (1,0) tile into (0,1)
__global__ void mirror_kernel()
{
    __shared__ float tile[32][33];
    float* Cb = g_C + (size_t)blockIdx.z * DOUT * DOUT;
    int sx = 128 + blockIdx.x * 32;
    int sy = blockIdx.y * 32;
    int tx = threadIdx.x, ty = threadIdx.y;
#pragma unroll
    for (int k = 0; k < 32; k += 8)
        tile[ty + k][tx] = Cb[(size_t)(sx + ty + k) * DOUT + sy + tx];
    __syncthreads();
#pragma unroll
    for (int k = 0; k < 32; k += 8)
        Cb[(size_t)(sy + ty + k) * DOUT + sx + tx] = tile[tx][ty + k];
}

// ---------------------------------------------------------------------------
// Pass 3: Lanczos(m=64) + CGS1 reorth, pipelined matvec, parallel Sturm.
// ---------------------------------------------------------------------------
__device__ __forceinline__ float blk_sum(float v, float* red)
{
#pragma unroll
    for (int o = 16; o; o >>= 1) v += __shfl_xor_sync(0xffffffffu, v, o);
    int lane = threadIdx.x & 31, wid = threadIdx.x >> 5;
    __syncthreads();
    if (lane == 0) red[wid] = v;
    __syncthreads();
    float s = red[0];
#pragma unroll
    for (int i = 1; i < 8; i++) s += red[i];
    return s;
}

__device__ __forceinline__ float blk_max(float v, float* red)
{
#pragma unroll
    for (int o = 16; o; o >>= 1) v = fmaxf(v, __shfl_xor_sync(0xffffffffu, v, o));
    int lane = threadIdx.x & 31, wid = threadIdx.x >> 5;
    __syncthreads();
    if (lane == 0) red[wid] = v;
    __syncthreads();
    float s = red[0];
#pragma unroll
    for (int i = 1; i < 8; i++) s = fmaxf(s, red[i]);
    return s;
}

__device__ __forceinline__ float blk_min(float v, float* red)
{
#pragma unroll
    for (int o = 16; o; o >>= 1) v = fminf(v, __shfl_xor_sync(0xffffffffu, v, o));
    int lane = threadIdx.x & 31, wid = threadIdx.x >> 5;
    __syncthreads();
    if (lane == 0) red[wid] = v;
    __syncthreads();
    float s = red[0];
#pragma unroll
    for (int i = 1; i < 8; i++) s = fminf(s, red[i]);
    return s;
}

__global__ void lanczos_kernel(float* __restrict__ out)
{
    extern __shared__ float sh[];
    float* V     = sh;                       // (MLAN+1) x 256
    float* wv    = V + (MLAN + 1) * 256;     // 256
    float* alpha = wv + 256;                 // MLAN
    float* beta  = alpha + MLAN;             // MLAN
    float* coef  = beta + MLAN;              // MLAN
    float* yv    = coef + MLAN;              // MLAN
    float* tdd   = yv + MLAN;                // MLAN (bsq scratch, then LU)
    float* tu1   = tdd + MLAN;               // MLAN
    float* tu2   = tu1 + MLAN;               // MLAN
    float* red   = tu2 + MLAN;               // 8
    float* ssc   = red + 8;                  // 8

    __shared__ int midx;

    int t = threadIdx.x;
    int lane = t & 31, wid = t >> 5;
    int b = blockIdx.x;
    const float* C = g_C + (size_t)b * DOUT * DOUT;

    float x = __sinf((float)t * 1.7f + 0.5f) + 0.01f;
    float nn = blk_sum(x * x, red);
    x *= rsqrtf(nn);
    V[t] = x;
    __syncthreads();

    int m_eff = MLAN;
    int rbase = wid * 32;
    for (int j = 0; j < MLAN; j++) {
        // ---- matvec: wv = C * V[j], 8 interleaved rows per warp-round ----
        {
            const float4* v4 = (const float4*)(V + j * 256);
            float4 va = v4[lane];
            float4 vb = v4[lane + 32];
#pragma unroll
            for (int r0 = 0; r0 < 32; r0 += 8) {
                float4 c1[8], c2[8];
#pragma unroll
                for (int i = 0; i < 8; i++) {
                    const float4* r4 = (const float4*)(C + (size_t)(rbase + r0 + i) * 256);
                    c1[i] = __ldg(r4 + lane);
                    c2[i] = __ldg(r4 + lane + 32);
                }
                float s[8];
#pragma unroll
                for (int i = 0; i < 8; i++) {
                    s[i] = c1[i].x*va.x + c1[i].y*va.y + c1[i].z*va.z + c1[i].w*va.w
                         + c2[i].x*vb.x + c2[i].y*vb.y + c2[i].z*vb.z + c2[i].w*vb.w;
                }
#pragma unroll
                for (int o = 16; o; o >>= 1) {
#pragma unroll
                    for (int i = 0; i < 8; i++)
                        s[i] += __shfl_xor_sync(0xffffffffu, s[i], o);
                }
                if (lane < 8) wv[rbase + r0 + lane] = s[lane];
            }
        }
        __syncthreads();

        float a = blk_sum(V[j * 256 + t] * wv[t], red);
        if (t == 0) alpha[j] = a;

        float wnew = wv[t] - a * V[j * 256 + t];
        if (j > 0) wnew -= beta[j - 1] * V[(j - 1) * 256 + t];

        // ---- CGS single-pass full reorthogonalization ----
        {
            __syncthreads();
            wv[t] = wnew;
            __syncthreads();
            float4 wa = ((const float4*)wv)[lane];
            float4 wb = ((const float4*)wv)[lane + 32];
            for (int i0 = wid * 4; i0 <= j; i0 += 32) {
                float s[4];
#pragma unroll
                for (int q = 0; q < 4; q++) {
                    int iq = (i0 + q <= j) ? (i0 + q) : j;
                    const float4* vi4 = (const float4*)(V + iq * 256);
                    float4 c1 = vi4[lane], c2 = vi4[lane + 32];
                    s[q] = c1.x*wa.x + c1.y*wa.y + c1.z*wa.z + c1.w*wa.w
                         + c2.x*wb.x + c2.y*wb.y + c2.z*wb.z + c2.w*wb.w;
                }
#pragma unroll
                for (int o = 16; o; o >>= 1) {
                    s[0] += __shfl_xor_sync(0xffffffffu, s[0], o);
                    s[1] += __shfl_xor_sync(0xffffffffu, s[1], o);
                    s[2] += __shfl_xor_sync(0xffffffffu, s[2], o);
                    s[3] += __shfl_xor_sync(0xffffffffu, s[3], o);
                }
                if (lane == 0) {
#pragma unroll
                    for (int q = 0; q < 4; q++)
                        if (i0 + q <= j) coef[i0 + q] = s[q];
                }
            }
            __syncthreads();
            float cr0 = 0.f, cr1 = 0.f, cr2 = 0.f, cr3 = 0.f;
            int i = 0;
            for (; i + 3 <= j; i += 4) {
                cr0 += coef[i]     * V[i * 256 + t];
                cr1 += coef[i + 1] * V[(i + 1) * 256 + t];
                cr2 += coef[i + 2] * V[(i + 2) * 256 + t];
                cr3 += coef[i + 3] * V[(i + 3) * 256 + t];
            }
            for (; i <= j; i++) cr0 += coef[i] * V[i * 256 + t];
            wnew = wv[t] - ((cr0 + cr1) + (cr2 + cr3));
        }

        float b2 = blk_sum(wnew * wnew, red);
        float bn = sqrtf(b2);
        if (bn < 1e-20f) { m_eff = j + 1; break; }
        if (t == 0) beta[j] = bn;
        V[(j + 1) * 256 + t] = wnew / bn;
        __syncthreads();
    }

    int m = m_eff;

    // ---- Gershgorin bounds ----
    float gl = 1e30f, gh = -1e30f;
    if (t < m) {
        float r = (t > 0 ? fabsf(beta[t - 1]) : 0.f) + (t < m - 1 ? fabsf(beta[t]) : 0.f);
        gl = alpha[t] - r;
        gh = alpha[t] + r;
    }
    float lo = blk_min(gl, red);
    float hi = blk_max(gh, red);

    if (t < m - 1) tdd[t] = beta[t] * beta[t];
    __syncthreads();

    // ---- parallel Sturm: 256 points x 3 rounds ----
    for (int r = 0; r < 3; r++) {
        float xx = lo + (hi - lo) * ((float)(t + 1) * (1.f / 257.f));
        int cnt = 0;
        float d = alpha[0] - xx;
        if (d < 0.f) cnt++;
        for (int i = 1; i < m; i++) {
            if (fabsf(d) < 1e-30f) d = (d < 0.f) ? -1e-30f : 1e-30f;
            d = alpha[i] - xx - __fdividef(tdd[i - 1], d);
            if (d < 0.f) cnt++;
        }
        float cl = (cnt < m)  ? xx : -1e30f;
        float ch = (cnt >= m) ? xx :  1e30f;
        float nl = blk_max(cl, red);
        float nh = blk_min(ch, red);
        lo = fmaxf(lo, nl);
        hi = fminf(hi, nh);
    }
    float lam = 0.5f * (lo + hi);
    __syncthreads();

    // ---- inverse iteration (serial, thread 0) ----
    if (t == 0) {
        for (int it = 0; it < 2; it++) {
            if (it == 0) for (int i = 0; i < m; i++) yv[i] = 1.f;
            for (int i = 0; i < m; i++) {
                tdd[i] = alpha[i] - lam;
                tu1[i] = (i < m - 1) ? beta[i] : 0.f;
                tu2[i] = 0.f;
            }
            for (int i = 0; i < m - 1; i++) {
                float p = tdd[i], q = tu1[i], rr = tu2[i];
                float s = beta[i];
                float uu = tdd[i + 1], vvv = tu1[i + 1];
                float yi = yv[i], yi1 = yv[i + 1];
                if (fabsf(s) > fabsf(p)) {
                    float tmp;
                    tmp = p; p = s; s = tmp;
                    tmp = q; q = uu; uu = tmp;
                    tmp = rr; rr = vvv; vvv = tmp;
                    tmp = yi; yi = yi1; yi1 = tmp;
                }
                if (p == 0.f) p = 1e-30f;
                float mf = s / p;
                tdd[i] = p; tu1[i] = q; tu2[i] = rr; yv[i] = yi;
                tdd[i + 1] = uu - mf * q;
                tu1[i + 1] = vvv - mf * rr;
                tu2[i + 1] = 0.f;
                yv[i + 1] = yi1 - mf * yi;
            }
            if (tdd[m - 1] == 0.f) tdd[m - 1] = 1e-30f;
            yv[m - 1] /= tdd[m - 1];
            if (m >= 2) yv[m - 2] = (yv[m - 2] - tu1[m - 2] * yv[m - 1]) / tdd[m - 2];
            for (int i = m - 3; i >= 0; i--)
                yv[i] = (yv[i] - tu1[i] * yv[i + 1] - tu2[i] * yv[i + 2]) / tdd[i];
            float s2 = 0.f;
            for (int i = 0; i < m; i++) s2 += yv[i] * yv[i];
            float inv = rsqrtf(s2);
            for (int i = 0; i < m; i++) yv[i] *= inv;
        }
        midx = 1 << 30;
    }
    __syncthreads();

    // Ritz vector
    float vr0 = 0.f, vr1 = 0.f, vr2 = 0.f, vr3 = 0.f;
    {
        int i = 0;
        for (; i + 3 < m; i += 4) {
            vr0 += yv[i]     * V[i * 256 + t];
            vr1 += yv[i + 1] * V[(i + 1) * 256 + t];
            vr2 += yv[i + 2] * V[(i + 2) * 256 + t];
            vr3 += yv[i + 3] * V[(i + 3) * 256 + t];
        }
        for (; i < m; i++) vr0 += yv[i] * V[i * 256 + t];
    }
    float vr = (vr0 + vr1) + (vr2 + vr3);
    float n2 = blk_sum(vr * vr, red);
    vr *= rsqrtf(n2);

    float av = fabsf(vr);
    float mx = blk_max(av, red);
    if (av == mx) atomicMin(&midx, t);
    __syncthreads();
    if (t == midx) ssc[0] = (vr >= 0.f) ? 1.f : -1.f;
    __syncthreads();

    out[(size_t)b * 256 + t] = vr * ssc[0];
}

// ---------------------------------------------------------------------------
extern "C" void kernel_launch(void* const* d_in, const int* in_sizes, int n_in,
                              void* d_out, int out_size)
{
    const float* caps = (const float*)d_in[0];   // (64, 2048, 16)
    const float* W    = (const float*)d_in[1];   // (2048, 16, 256)
    float* out        = (float*)d_out;           // (64, 16, 16)

    dim3 g1(NCAPS, 4);
    u_kernel<<<g1, 256>>>(caps, W);

    dim3 g2(3, KSPLIT, BATCH);
    syrk_kernel<<<g2, 256>>>();

    dim3 gr(3, BATCH);
    reduce_kernel<<<gr, 256>>>();

    dim3 gm(4, 4, BATCH);
    mirror_kernel<<<gm, dim3(32, 8)>>>();

    size_t smem = ((MLAN + 1) * 256 + 256 + 7 * MLAN + 16) * sizeof(float);
    cudaFuncSetAttribute(lanczos_kernel, cudaFuncAttributeMaxDynamicSharedMemorySize, (int)smem);
    lanczos_kernel<<<BATCH, 256, smem>>>(out);
}

// round 9
// speedup vs baseline: 3.1987x; 1.3175x over previous
#include <cuda_runtime.h>
#include <math.h>

#define BATCH 64
#define NCAPS 2048
#define IDIM 16
#define DOUT 256
#define MLAN 48
#define KSPLIT 3

typedef unsigned long long u64;

__device__ float g_u[(size_t)BATCH * NCAPS * DOUT];              // 134 MB
__device__ float g_C[(size_t)BATCH * DOUT * DOUT];               // 16 MB
__device__ float g_Cp[KSPLIT][(size_t)BATCH * DOUT * DOUT];      // 48 MB partials

// ---------------- packed f32x2 helpers ----------------
__device__ __forceinline__ void ffma2(u64 &d, u64 a, u64 b) {
    asm("fma.rn.f32x2 %0, %1, %2, %0;" : "+l"(d) : "l"(a), "l"(b));
}
__device__ __forceinline__ u64 pack2(float x, float y) {
    u64 r; asm("mov.b64 %0, {%1, %2};" : "=l"(r) : "f"(x), "f"(y)); return r;
}
__device__ __forceinline__ void unpack2(float &x, float &y, u64 v) {
    asm("mov.b64 {%0, %1}, %2;" : "=f"(x), "=f"(y) : "l"(v));
}

// ---------------------------------------------------------------------------
// Pass 1: u[b,c,o] = sum_i caps[b,c,i] * W[c,i,o]
// grid (NCAPS, 2): 32 batches per block
// ---------------------------------------------------------------------------
__global__ void u_kernel(const float* __restrict__ caps, const float* __restrict__ W)
{
    int c  = blockIdx.x;
    int b0 = blockIdx.y * 32;
    __shared__ __align__(16) float caps_s[32][IDIM];
    __shared__ __align__(16) float w_s[IDIM][DOUT];
    int t = threadIdx.x;

    for (int idx = t; idx < 32 * IDIM; idx += 256) {
        int b = idx >> 4, i = idx & 15;
        caps_s[b][i] = caps[(size_t)(b0 + b) * (NCAPS * IDIM) + (size_t)c * IDIM + i];
    }
    for (int idx = t; idx < IDIM * DOUT; idx += 256)
        ((float*)w_s)[idx] = W[(size_t)c * (IDIM * DOUT) + idx];
    __syncthreads();

    float wr[IDIM];
#pragma unroll
    for (int i = 0; i < IDIM; i++) wr[i] = w_s[i][t];

#pragma unroll 4
    for (int b = 0; b < 32; b++) {
        const float4* cp = (const float4*)caps_s[b];
        float acc = 0.f;
#pragma unroll
        for (int q = 0; q < 4; q++) {
            float4 cv = cp[q];
            acc += cv.x * wr[q * 4 + 0] + cv.y * wr[q * 4 + 1]
                 + cv.z * wr[q * 4 + 2] + cv.w * wr[q * 4 + 3];
        }
        g_u[(size_t)(b0 + b) * (NCAPS * DOUT) + (size_t)c * DOUT + t] = acc;
    }
}

// ---------------------------------------------------------------------------
// Pass 2: SYRK, K-split x3, 3 symmetric tiles. f32x2 packed FMA.
// ---------------------------------------------------------------------------
#define BK 16
__global__ void __launch_bounds__(256, 2) syrk_kernel()
{
    int b = blockIdx.z;
    int which = blockIdx.x;
    int ks = blockIdx.y;
    int d0 = (which == 0) ? 0 : 128;
    int e0 = (which == 1) ? 128 : 0;
    int kbeg = ks * 688;
    int kend = (ks == KSPLIT - 1) ? NCAPS : kbeg + 688;

    __shared__ __align__(16) float As[BK][128];
    __shared__ __align__(16) float Bs[BK][128];
    int t = threadIdx.x;
    int tx = t & 15, ty = t >> 4;

    const float* ub = g_u + (size_t)b * NCAPS * DOUT;

    u64 acc2[8][4];
#pragma unroll
    for (int i = 0; i < 8; i++)
#pragma unroll
        for (int j = 0; j < 4; j++) acc2[i][j] = 0ull;

    for (int c0 = kbeg; c0 < kend; c0 += BK) {
#pragma unroll
        for (int l = 0; l < 2; l++) {
            int idx = t + l * 256;
            int r = idx >> 5, cc = (idx & 31) * 4;
            *(float4*)&As[r][cc] = *(const float4*)&ub[(size_t)(c0 + r) * DOUT + d0 + cc];
            *(float4*)&Bs[r][cc] = *(const float4*)&ub[(size_t)(c0 + r) * DOUT + e0 + cc];
        }
        __syncthreads();
#pragma unroll
        for (int k = 0; k < BK; k++) {
            float4 A1 = *(float4*)&As[k][ty * 8];
            float4 A2 = *(float4*)&As[k][ty * 8 + 4];
            float4 B1 = *(float4*)&Bs[k][tx * 8];
            float4 B2 = *(float4*)&Bs[k][tx * 8 + 4];
            u64 b2[4] = { pack2(B1.x, B1.y), pack2(B1.z, B1.w),
                          pack2(B2.x, B2.y), pack2(B2.z, B2.w) };
            float a[8] = {A1.x, A1.y, A1.z, A1.w, A2.x, A2.y, A2.z, A2.w};
#pragma unroll
            for (int i = 0; i < 8; i++) {
                u64 ad = pack2(a[i], a[i]);
#pragma unroll
                for (int j = 0; j < 4; j++) ffma2(acc2[i][j], ad, b2[j]);
            }
        }
        __syncthreads();
    }

    float* Cb = g_Cp[ks] + (size_t)b * DOUT * DOUT;
#pragma unroll
    for (int i = 0; i < 8; i++) {
        int d = d0 + ty * 8 + i;
        float v[8];
#pragma unroll
        for (int j = 0; j < 4; j++) unpack2(v[2 * j], v[2 * j + 1], acc2[i][j]);
        *(float4*)&Cb[(size_t)d * DOUT + e0 + tx * 8]     = make_float4(v[0], v[1], v[2], v[3]);
        *(float4*)&Cb[(size_t)d * DOUT + e0 + tx * 8 + 4] = make_float4(v[4], v[5], v[6], v[7]);
    }
}

// sum the 3 K-split partials (deterministic)
__global__ void reduce_kernel()
{
    int b = blockIdx.y;
    int which = blockIdx.x;
    int d0 = (which == 0) ? 0 : 128;
    int e0 = (which == 1) ? 128 : 0;
    size_t base = (size_t)b * DOUT * DOUT;
    int t = threadIdx.x;
    for (int i = t; i < 128 * 32; i += 256) {
        int r = i >> 5, c4 = (i & 31);
        size_t off = base + (size_t)(d0 + r) * DOUT + e0 + c4 * 4;
        float4 a = *(const float4*)&g_Cp[0][off];
        float4 bb = *(const float4*)&g_Cp[1][off];
        float4 c = *(const float4*)&g_Cp[2][off];
        float4 s = make_float4(a.x + bb.x + c.x, a.y + bb.y + c.y,
                               a.z + bb.z + c.z, a.w + bb.w + c.w);
        *(float4*)&g_C[off] = s;
    }
}

// mirror (1,0) tile into (0,1)
__global__ void mirror_kernel()
{
    __shared__ float tile[32][33];
    float* Cb = g_C + (size_t)blockIdx.z * DOUT * DOUT;
    int sx = 128 + blockIdx.x * 32;
    int sy = blockIdx.y * 32;
    int tx = threadIdx.x, ty = threadIdx.y;
#pragma unroll
    for (int k = 0; k < 32; k += 8)
        tile[ty + k][tx] = Cb[(size_t)(sx + ty + k) * DOUT + sy + tx];
    __syncthreads();
#pragma unroll
    for (int k = 0; k < 32; k += 8)
        Cb[(size_t)(sy + ty + k) * DOUT + sx + tx] = tile[tx][ty + k];
}

// ---------------------------------------------------------------------------
// Pass 3: Lanczos(m=48), 512 threads/block, CGS1, parallel Sturm.
// ---------------------------------------------------------------------------
#define NWARP 16
__device__ __forceinline__ float blk_sum512(float v, float* red)
{
#pragma unroll
    for (int o = 16; o; o >>= 1) v += __shfl_xor_sync(0xffffffffu, v, o);
    int lane = threadIdx.x & 31, wid = threadIdx.x >> 5;
    __syncthreads();
    if (lane == 0) red[wid] = v;
    __syncthreads();
    float s = red[0];
#pragma unroll
    for (int i = 1; i < NWARP; i++) s += red[i];
    return s;
}

__device__ __forceinline__ float blk_max512(float v, float* red)
{
#pragma unroll
    for (int o = 16; o; o >>= 1) v = fmaxf(v, __shfl_xor_sync(0xffffffffu, v, o));
    int lane = threadIdx.x & 31, wid = threadIdx.x >> 5;
    __syncthreads();
    if (lane == 0) red[wid] = v;
    __syncthreads();
    float s = red[0];
#pragma unroll
    for (int i = 1; i < NWARP; i++) s = fmaxf(s, red[i]);
    return s;
}

__device__ __forceinline__ float blk_min512(float v, float* red)
{
#pragma unroll
    for (int o = 16; o; o >>= 1) v = fminf(v, __shfl_xor_sync(0xffffffffu, v, o));
    int lane = threadIdx.x & 31, wid = threadIdx.x >> 5;
    __syncthreads();
    if (lane == 0) red[wid] = v;
    __syncthreads();
    float s = red[0];
#pragma unroll
    for (int i = 1; i < NWARP; i++) s = fminf(s, red[i]);
    return s;
}

__global__ void __launch_bounds__(512, 1) lanczos_kernel(float* __restrict__ out)
{
    extern __shared__ float sh[];
    float* V     = sh;                       // (MLAN+1) x 256
    float* wv    = V + (MLAN + 1) * 256;     // 256
    float* cbuf  = wv + 256;                 // 512 (split-axpy partials)
    float* alpha = cbuf + 512;               // MLAN
    float* beta  = alpha + MLAN;             // MLAN
    float* coef  = beta + MLAN;              // MLAN
    float* yv    = coef + MLAN;              // MLAN
    float* tdd   = yv + MLAN;                // MLAN
    float* tu1   = tdd + MLAN;               // MLAN
    float* tu2   = tu1 + MLAN;               // MLAN
    float* red   = tu2 + MLAN;               // NWARP
    float* ssc   = red + NWARP;              // 8

    __shared__ int midx;

    int t = threadIdx.x;
    int lane = t & 31, wid = t >> 5;
    int e = t & 255;          // vector element owned (both halves)
    int half = t >> 8;        // 0 or 1
    int b = blockIdx.x;
    const float* C = g_C + (size_t)b * DOUT * DOUT;

    // start vector (only t<256 meaningful)
    float x = __sinf((float)e * 1.7f + 0.5f) + 0.01f;
    float nn = blk_sum512((t < 256) ? x * x : 0.f, red);
    x *= rsqrtf(nn);
    if (t < 256) V[t] = x;
    __syncthreads();

    int m_eff = MLAN;
    int rbase = wid * 16;     // 16 warps x 16 rows
    for (int j = 0; j < MLAN; j++) {
        // ---- matvec: wv = C*V[j]; 16 warps, 2 rounds of 8 rows ----
        {
            const float4* v4 = (const float4*)(V + j * 256);
            float4 va = v4[lane];
            float4 vb = v4[lane + 32];
#pragma unroll
            for (int r0 = 0; r0 < 16; r0 += 8) {
                float4 c1[8], c2[8];
#pragma unroll
                for (int i = 0; i < 8; i++) {
                    const float4* r4 = (const float4*)(C + (size_t)(rbase + r0 + i) * 256);
                    c1[i] = __ldg(r4 + lane);
                    c2[i] = __ldg(r4 + lane + 32);
                }
                float s[8];
#pragma unroll
                for (int i = 0; i < 8; i++) {
                    s[i] = c1[i].x*va.x + c1[i].y*va.y + c1[i].z*va.z + c1[i].w*va.w
                         + c2[i].x*vb.x + c2[i].y*vb.y + c2[i].z*vb.z + c2[i].w*vb.w;
                }
#pragma unroll
                for (int o = 16; o; o >>= 1) {
#pragma unroll
                    for (int i = 0; i < 8; i++)
                        s[i] += __shfl_xor_sync(0xffffffffu, s[i], o);
                }
                if (lane < 8) wv[rbase + r0 + lane] = s[lane];
            }
        }
        __syncthreads();

        float a = blk_sum512((t < 256) ? V[j * 256 + t] * wv[t] : 0.f, red);
        if (t == 0) alpha[j] = a;

        float wnew = 0.f;
        if (t < 256) {
            wnew = wv[t] - a * V[j * 256 + t];
            if (j > 0) wnew -= beta[j - 1] * V[(j - 1) * 256 + t];
        }

        // ---- CGS1 full reorth ----
        {
            __syncthreads();
            if (t < 256) wv[t] = wnew;
            __syncthreads();
            float4 wa = ((const float4*)wv)[lane];
            float4 wb = ((const float4*)wv)[lane + 32];
            // 16 warps x 4 dots: covers i0 in [0,64) in one round (j <= 47)
            {
                int i0 = wid * 4;
                if (i0 <= j) {
                    float s[4];
#pragma unroll
                    for (int q = 0; q < 4; q++) {
                        int iq = (i0 + q <= j) ? (i0 + q) : j;
                        const float4* vi4 = (const float4*)(V + iq * 256);
                        float4 c1 = vi4[lane], c2 = vi4[lane + 32];
                        s[q] = c1.x*wa.x + c1.y*wa.y + c1.z*wa.z + c1.w*wa.w
                             + c2.x*wb.x + c2.y*wb.y + c2.z*wb.z + c2.w*wb.w;
                    }
#pragma unroll
                    for (int o = 16; o; o >>= 1) {
                        s[0] += __shfl_xor_sync(0xffffffffu, s[0], o);
                        s[1] += __shfl_xor_sync(0xffffffffu, s[1], o);
                        s[2] += __shfl_xor_sync(0xffffffffu, s[2], o);
                        s[3] += __shfl_xor_sync(0xffffffffu, s[3], o);
                    }
                    if (lane == 0) {
#pragma unroll
                        for (int q = 0; q < 4; q++)
                            if (i0 + q <= j) coef[i0 + q] = s[q];
                    }
                }
            }
            __syncthreads();
            // split axpy: half 0 sums i in [0,(j+1)/2), half 1 the rest
            int ibeg = half ? ((j + 1) >> 1) : 0;
            int iend = half ? (j + 1) : ((j + 1) >> 1);
            float cr0 = 0.f, cr1 = 0.f, cr2 = 0.f, cr3 = 0.f;
            int i = ibeg;
            for (; i + 3 < iend; i += 4) {
                cr0 += coef[i]     * V[i * 256 + e];
                cr1 += coef[i + 1] * V[(i + 1) * 256 + e];
                cr2 += coef[i + 2] * V[(i + 2) * 256 + e];
                cr3 += coef[i + 3] * V[(i + 3) * 256 + e];
            }
            for (; i < iend; i++) cr0 += coef[i] * V[i * 256 + e];
            cbuf[t] = (cr0 + cr1) + (cr2 + cr3);
            __syncthreads();
            if (t < 256) wnew = wv[t] - (cbuf[t] + cbuf[t + 256]);
        }

        float b2 = blk_sum512((t < 256) ? wnew * wnew : 0.f, red);
        float bn = sqrtf(b2);
        if (bn < 1e-20f) { m_eff = j + 1; break; }
        if (t == 0) beta[j] = bn;
        if (t < 256) V[(j + 1) * 256 + t] = wnew / bn;
        __syncthreads();
    }

    int m = m_eff;

    // ---- Gershgorin bounds ----
    float gl = 1e30f, gh = -1e30f;
    if (t < m) {
        float r = (t > 0 ? fabsf(beta[t - 1]) : 0.f) + (t < m - 1 ? fabsf(beta[t]) : 0.f);
        gl = alpha[t] - r;
        gh = alpha[t] + r;
    }
    float lo = blk_min512(gl, red);
    float hi = blk_max512(gh, red);

    if (t < m - 1) tdd[t] = beta[t] * beta[t];
    __syncthreads();

    // ---- parallel Sturm: 512 points x 3 rounds ----
    for (int r = 0; r < 3; r++) {
        float xx = lo + (hi - lo) * ((float)(t + 1) * (1.f / 513.f));
        int cnt = 0;
        float d = alpha[0] - xx;
        if (d < 0.f) cnt++;
        for (int i = 1; i < m; i++) {
            if (fabsf(d) < 1e-30f) d = (d < 0.f) ? -1e-30f : 1e-30f;
            d = alpha[i] - xx - __fdividef(tdd[i - 1], d);
            if (d < 0.f) cnt++;
        }
        float cl = (cnt < m)  ? xx : -1e30f;
        float ch = (cnt >= m) ? xx :  1e30f;
        float nl = blk_max512(cl, red);
        float nh = blk_min512(ch, red);
        lo = fmaxf(lo, nl);
        hi = fminf(hi, nh);
    }
    float lam = 0.5f * (lo + hi);
    __syncthreads();

    // ---- inverse iteration (serial, thread 0) ----
    if (t == 0) {
        for (int it = 0; it < 2; it++) {
            if (it == 0) for (int i = 0; i < m; i++) yv[i] = 1.f;
            for (int i = 0; i < m; i++) {
                tdd[i] = alpha[i] - lam;
                tu1[i] = (i < m - 1) ? beta[i] : 0.f;
                tu2[i] = 0.f;
            }
            for (int i = 0; i < m - 1; i++) {
                float p = tdd[i], q = tu1[i], rr = tu2[i];
                float s = beta[i];
                float uu = tdd[i + 1], vvv = tu1[i + 1];
                float yi = yv[i], yi1 = yv[i + 1];
                if (fabsf(s) > fabsf(p)) {
                    float tmp;
                    tmp = p; p = s; s = tmp;
                    tmp = q; q = uu; uu = tmp;
                    tmp = rr; rr = vvv; vvv = tmp;
                    tmp = yi; yi = yi1; yi1 = tmp;
                }
                if (p == 0.f) p = 1e-30f;
                float mf = s / p;
                tdd[i] = p; tu1[i] = q; tu2[i] = rr; yv[i] = yi;
                tdd[i + 1] = uu - mf * q;
                tu1[i + 1] = vvv - mf * rr;
                tu2[i + 1] = 0.f;
                yv[i + 1] = yi1 - mf * yi;
            }
            if (tdd[m - 1] == 0.f) tdd[m - 1] = 1e-30f;
            yv[m - 1] /= tdd[m - 1];
            if (m >= 2) yv[m - 2] = (yv[m - 2] - tu1[m - 2] * yv[m - 1]) / tdd[m - 2];
            for (int i = m - 3; i >= 0; i--)
                yv[i] = (yv[i] - tu1[i] * yv[i + 1] - tu2[i] * yv[i + 2]) / tdd[i];
            float s2 = 0.f;
            for (int i = 0; i < m; i++) s2 += yv[i] * yv[i];
            float inv = rsqrtf(s2);
            for (int i = 0; i < m; i++) yv[i] *= inv;
        }
        midx = 1 << 30;
    }
    __syncthreads();

    // ---- Ritz vector (split across halves) ----
    {
        int ibeg = half ? (m >> 1) : 0;
        int iend = half ? m : (m >> 1);
        float v0 = 0.f, v1 = 0.f, v2 = 0.f, v3 = 0.f;
        int i = ibeg;
        for (; i + 3 < iend; i += 4) {
            v0 += yv[i]     * V[i * 256 + e];
            v1 += yv[i + 1] * V[(i + 1) * 256 + e];
            v2 += yv[i + 2] * V[(i + 2) * 256 + e];
            v3 += yv[i + 3] * V[(i + 3) * 256 + e];
        }
        for (; i < iend; i++) v0 += yv[i] * V[i * 256 + e];
        cbuf[t] = (v0 + v1) + (v2 + v3);
    }
    __syncthreads();
    float vr = cbuf[e] + cbuf[e + 256];
    float n2 = blk_sum512((t < 256) ? vr * vr : 0.f, red);
    vr *= rsqrtf(n2);

    float av = (t < 256) ? fabsf(vr) : -1.f;
    float mx = blk_max512(av, red);
    if (t < 256 && av == mx) atomicMin(&midx, t);
    __syncthreads();
    if (t == midx) ssc[0] = (vr >= 0.f) ? 1.f : -1.f;
    __syncthreads();

    if (t < 256) out[(size_t)b * 256 + t] = vr * ssc[0];
}

// ---------------------------------------------------------------------------
extern "C" void kernel_launch(void* const* d_in, const int* in_sizes, int n_in,
                              void* d_out, int out_size)
{
    const float* caps = (const float*)d_in[0];   // (64, 2048, 16)
    const float* W    = (const float*)d_in[1];   // (2048, 16, 256)
    float* out        = (float*)d_out;           // (64, 16, 16)

    dim3 g1(NCAPS, 2);
    u_kernel<<<g1, 256>>>(caps, W);

    dim3 g2(3, KSPLIT, BATCH);
    syrk_kernel<<<g2, 256>>>();

    dim3 gr(3, BATCH);
    reduce_kernel<<<gr, 256>>>();

    dim3 gm(4, 4, BATCH);
    mirror_kernel<<<gm, dim3(32, 8)>>>();

    size_t smem = ((MLAN + 1) * 256 + 256 + 512 + 7 * MLAN + NWARP + 8) * sizeof(float);
    cudaFuncSetAttribute(lanczos_kernel, cudaFuncAttributeMaxDynamicSharedMemorySize, (int)smem);
    lanczos_kernel<<<BATCH, 512, smem>>>(out);
}